// round 1
// baseline (speedup 1.0000x reference)
#include <cuda_runtime.h>
#include <cuda_bf16.h>

// Problem shape (fixed by the dataset): B=2, N=2048, K=48, A=4
// X:        (B, N, A, 3) float32   -> d_in[0]
// edge_idx: (B, N, K)    int32     -> d_in[1]
// C:        (B, N)       int32     -> d_in[2]
// out:      (B, N, K, 2A*2A*3=192) float32
//
// Per (b,n): build frame R from atoms N/CA/C, gather K neighbor rows,
// compute normalized pair-difference vectors among the 8 stacked atoms,
// rotate into frame, mask, write 192 floats per (b,n,k).

#define BB 2
#define NN 2048
#define KK 48
#define EPS 0.1f

#define THREADS 384   // KK * 8 (one thread per (k, a))

__global__ __launch_bounds__(THREADS) void edge_orient_kernel(
    const float* __restrict__ X,      // (B*N*12)
    const int*   __restrict__ E,      // (B*N*K)
    const int*   __restrict__ C,      // (B*N)
    float*       __restrict__ out)    // (B*N*K*192)
{
    const int bn = blockIdx.x;        // b*N + n
    const int b  = bn / NN;
    const int t  = threadIdx.x;

    __shared__ __align__(16) float sXj[KK][12];   // gathered neighbor atom coords
    __shared__ __align__(16) float sXi[12];       // self atom coords
    __shared__ float sR[9];                       // rows: n1, n2, n3
    __shared__ float sMaskJ[KK];
    __shared__ float sMaskI;

    const int* e_row = E + (size_t)bn * KK;

    // ---- staging phase ----
    if (t < 12) {
        sXi[t] = X[(size_t)bn * 12 + t];
    }
    if (t < KK * 3) {                 // 144 threads: one float4 each
        const int nb = t / 3;
        const int q  = t % 3;
        const int j  = e_row[nb];
        const float4* src = (const float4*)(X + ((size_t)(b * NN + j)) * 12);
        ((float4*)&sXj[nb][0])[q] = src[q];
    }
    if (t >= 144 && t < 144 + KK) {   // masks for neighbors
        const int nb = t - 144;
        const int j  = e_row[nb];
        sMaskJ[nb] = (C[b * NN + j] > 0) ? 1.0f : 0.0f;
    }
    if (t == 192) {
        sMaskI = (C[bn] > 0) ? 1.0f : 0.0f;
    }
    if (t == 193) {
        // Build rotation frame from atoms 0 (N), 1 (CA), 2 (C)
        const float* xr = X + (size_t)bn * 12;
        float Nx = xr[0], Ny = xr[1],  Nz = xr[2];
        float Ax = xr[3], Ay = xr[4],  Az = xr[5];
        float Cx = xr[6], Cy = xr[7],  Cz = xr[8];

        // u_CA_N = normed(X_N - X_CA)
        float ux = Nx - Ax, uy = Ny - Ay, uz = Nz - Az;
        float inv = rsqrtf(ux*ux + uy*uy + uz*uz + EPS);
        float n1x = ux*inv, n1y = uy*inv, n1z = uz*inv;

        // u_CA_C = normed(X_C - X_CA)
        float vx = Cx - Ax, vy = Cy - Ay, vz = Cz - Az;
        inv = rsqrtf(vx*vx + vy*vy + vz*vz + EPS);
        vx *= inv; vy *= inv; vz *= inv;

        // n2 = normed(cross(n1, u_CA_C))
        float c2x = n1y*vz - n1z*vy;
        float c2y = n1z*vx - n1x*vz;
        float c2z = n1x*vy - n1y*vx;
        inv = rsqrtf(c2x*c2x + c2y*c2y + c2z*c2z + EPS);
        float n2x = c2x*inv, n2y = c2y*inv, n2z = c2z*inv;

        // n3 = normed(cross(n1, n2))
        float c3x = n1y*n2z - n1z*n2y;
        float c3y = n1z*n2x - n1x*n2z;
        float c3z = n1x*n2y - n1y*n2x;
        inv = rsqrtf(c3x*c3x + c3y*c3y + c3z*c3z + EPS);
        float n3x = c3x*inv, n3y = c3y*inv, n3z = c3z*inv;

        sR[0] = n1x; sR[1] = n1y; sR[2] = n1z;
        sR[3] = n2x; sR[4] = n2y; sR[5] = n2z;
        sR[6] = n3x; sR[7] = n3y; sR[8] = n3z;
    }
    __syncthreads();

    // ---- compute phase: thread = (k, a) ----
    const int k = t >> 3;
    const int a = t & 7;

    const float* pa = (a < 4) ? &sXi[a * 3] : &sXj[k][(a - 4) * 3];
    const float ax = pa[0], ay = pa[1], az = pa[2];

    const float m = sMaskI * sMaskJ[k];

    const float n1x = sR[0], n1y = sR[1], n1z = sR[2];
    const float n2x = sR[3], n2y = sR[4], n2z = sR[5];
    const float n3x = sR[6], n3y = sR[7], n3z = sR[8];

    float res[24];
#pragma unroll
    for (int bq = 0; bq < 8; bq++) {
        const float* pb = (bq < 4) ? &sXi[bq * 3] : &sXj[k][(bq - 4) * 3];
        // U[a][b] = normed(x_b - x_a)
        const float dx = pb[0] - ax;
        const float dy = pb[1] - ay;
        const float dz = pb[2] - az;
        const float inv = rsqrtf(dx*dx + dy*dy + dz*dz + EPS) * m;  // fold mask
        const float ux = dx * inv, uy = dy * inv, uz = dz * inv;
        res[bq*3 + 0] = ux*n1x + uy*n1y + uz*n1z;
        res[bq*3 + 1] = ux*n2x + uy*n2y + uz*n2z;
        res[bq*3 + 2] = ux*n3x + uy*n3y + uz*n3z;
    }

    // 24 contiguous floats per thread -> 6x float4 stores (16B aligned: a*24*4 = 96B)
    float4* op = (float4*)(out + ((size_t)bn * KK + k) * 192 + a * 24);
#pragma unroll
    for (int q = 0; q < 6; q++) {
        op[q] = ((const float4*)res)[q];
    }
}

extern "C" void kernel_launch(void* const* d_in, const int* in_sizes, int n_in,
                              void* d_out, int out_size) {
    const float* X = (const float*)d_in[0];
    const int*   E = (const int*)d_in[1];
    const int*   C = (const int*)d_in[2];
    float* out = (float*)d_out;

    edge_orient_kernel<<<BB * NN, THREADS>>>(X, E, C, out);
}